// round 9
// baseline (speedup 1.0000x reference)
#include <cuda_runtime.h>

#define HW   3136
#define WD   56
#define NB   32
#define CIN  240
#define MID  120
#define COUT 480

// Scratch (allocation-free rule: __device__ globals)
__device__ float g_y1[(size_t)NB * MID * HW];   // conv1 output (post BN+ReLU)
__device__ float g_y2[(size_t)NB * MID * HW];   // depthwise output, SHUFFLED channel order

typedef unsigned long long u64;

__device__ __forceinline__ u64 fma2(u64 a, u64 b, u64 c) {
    u64 d; asm("fma.rn.f32x2 %0, %1, %2, %3;" : "=l"(d) : "l"(a), "l"(b), "l"(c)); return d;
}
__device__ __forceinline__ float2 unpack2(u64 v) {
    float2 r; asm("mov.b64 {%0, %1}, %2;" : "=f"(r.x), "=f"(r.y) : "l"(v)); return r;
}

// ---------------------------------------------------------------------------
// K1: grouped 1x1 conv (per group: 40oc x 80ic) + BN + ReLU -> g_y1
// grid (49, 3, 32), block 160.  Tile 40oc x 64hw, K=80 in 5 tiles of 16.
// W stored DUPLICATED in smem so LDS.64 yields {w,w}; X pairs free via float4.
// Double-buffered: LDG(t+1) -> compute(t) -> STS(t+1) -> sync.
// ---------------------------------------------------------------------------
__global__ __launch_bounds__(160) void conv1_kernel(
    const float* __restrict__ x, const float* __restrict__ w1,
    const float* __restrict__ scale1, const float* __restrict__ shift1)
{
    __shared__ __align__(16) float sX[2][16][64];
    __shared__ __align__(16) float sW[2][16][80];   // 40 oc duplicated
    const int tid = threadIdx.x;
    const int tx = tid & 15, ty = tid >> 4;          // tx: 4hw, ty: 4oc (0..9)
    const int n = blockIdx.z, g = blockIdx.y;
    const int hw0 = blockIdx.x * 64;
    const float* xg = x + ((size_t)n * CIN + g * 80) * HW;
    const float* wg = w1 + g * 40 * 80;

    u64 acc[4][2];
    #pragma unroll
    for (int i = 0; i < 4; i++) { acc[i][0] = 0ull; acc[i][1] = 0ull; }

    float rX[7], rW[4];

    auto ldg_tile = [&](int t) {
        const int kk = t * 16;
        #pragma unroll
        for (int i = 0; i < 7; i++) {
            int idx = tid + i * 160;
            if (idx < 1024) {
                int k = idx >> 6, j = idx & 63;
                rX[i] = xg[(size_t)(kk + k) * HW + hw0 + j];
            }
        }
        #pragma unroll
        for (int i = 0; i < 4; i++) {           // 16*40 = 640 = 4*160
            int idx = tid + i * 160;
            int oc = idx >> 4, k = idx & 15;
            rW[i] = wg[oc * 80 + kk + k];
        }
    };
    auto sts_tile = [&](int b) {
        #pragma unroll
        for (int i = 0; i < 7; i++) {
            int idx = tid + i * 160;
            if (idx < 1024) { int k = idx >> 6, j = idx & 63; sX[b][k][j] = rX[i]; }
        }
        #pragma unroll
        for (int i = 0; i < 4; i++) {
            int idx = tid + i * 160;
            int oc = idx >> 4, k = idx & 15;
            sW[b][k][2 * oc] = rW[i];
            sW[b][k][2 * oc + 1] = rW[i];
        }
    };
    auto compute = [&](int b) {
        #pragma unroll
        for (int k = 0; k < 16; k++) {
            const ulonglong2 w01 = *(const ulonglong2*)&sW[b][k][ty * 8];
            const ulonglong2 w23 = *(const ulonglong2*)&sW[b][k][ty * 8 + 4];
            const ulonglong2 xp  = *(const ulonglong2*)&sX[b][k][tx * 4];
            acc[0][0] = fma2(w01.x, xp.x, acc[0][0]); acc[0][1] = fma2(w01.x, xp.y, acc[0][1]);
            acc[1][0] = fma2(w01.y, xp.x, acc[1][0]); acc[1][1] = fma2(w01.y, xp.y, acc[1][1]);
            acc[2][0] = fma2(w23.x, xp.x, acc[2][0]); acc[2][1] = fma2(w23.x, xp.y, acc[2][1]);
            acc[3][0] = fma2(w23.y, xp.x, acc[3][0]); acc[3][1] = fma2(w23.y, xp.y, acc[3][1]);
        }
    };

    ldg_tile(0); sts_tile(0); __syncthreads();
    #pragma unroll
    for (int t = 0; t < 5; t++) {
        int b = t & 1;
        if (t + 1 < 5) ldg_tile(t + 1);
        compute(b);
        if (t + 1 < 5) sts_tile(b ^ 1);
        __syncthreads();
    }

    float* yb = g_y1 + (size_t)n * MID * HW;
    #pragma unroll
    for (int i = 0; i < 4; i++) {
        int oc = g * 40 + ty * 4 + i;
        float sc = scale1[oc], sh = shift1[oc];
        float2 v0 = unpack2(acc[i][0]), v1 = unpack2(acc[i][1]);
        float4 o;
        o.x = fmaxf(fmaf(v0.x, sc, sh), 0.f);
        o.y = fmaxf(fmaf(v0.y, sc, sh), 0.f);
        o.z = fmaxf(fmaf(v1.x, sc, sh), 0.f);
        o.w = fmaxf(fmaf(v1.y, sc, sh), 0.f);
        *(float4*)&yb[(size_t)oc * HW + hw0 + tx * 4] = o;
    }
}

// ---------------------------------------------------------------------------
// K2: depthwise 3x3 (pad 1) + BN2, write in SHUFFLED channel order.
// source c writes to dst = (c%40)*3 + c/40
// ---------------------------------------------------------------------------
__global__ __launch_bounds__(256) void dw_kernel(
    const float* __restrict__ w2, const float* __restrict__ scale2,
    const float* __restrict__ shift2)
{
    const int n = blockIdx.z, c = blockIdx.y;
    const int p = blockIdx.x * 256 + threadIdx.x;
    if (p >= HW) return;
    const int h = p / WD, w = p % WD;
    const float* src = g_y1 + ((size_t)n * MID + c) * HW;
    const float* wr = w2 + c * 9;
    float s = 0.f;
    #pragma unroll
    for (int kh = 0; kh < 3; kh++) {
        int hh = h + kh - 1;
        if (hh < 0 || hh >= WD) continue;
        const float* row = src + hh * WD;
        #pragma unroll
        for (int kw = 0; kw < 3; kw++) {
            int ww = w + kw - 1;
            if (ww >= 0 && ww < WD) s = fmaf(row[ww], wr[kh * 3 + kw], s);
        }
    }
    float v = fmaf(s, scale2[c], shift2[c]);
    const int dst = (c % 40) * 3 + c / 40;
    g_y2[((size_t)n * MID + dst) * HW + p] = v;
}

// ---------------------------------------------------------------------------
// K3: grouped 1x1 conv3 (40 shuffled ic) + BN3 + ReLU, plus full 1x1 shortcut
// (240 ic) + BN_sc, fused add -> out.
// grid (49, 6, 32), block 160.  Tile 80oc x 64hw; per-thread 8oc x 4hw.
// Unified 18-tile K pipeline: tiles 0..2 = conv3 (K 0..47, guarded at 40),
// tiles 3..17 = shortcut (K 0..239).  BN3+ReLU conversion after tile 2.
// Dup-W smem + float4 hw-pairs => inner loop is 16 FFMA2 + 5 LDS, zero MOVs.
// ---------------------------------------------------------------------------
__global__ __launch_bounds__(160) void conv3_kernel(
    const float* __restrict__ x,
    const float* __restrict__ w3, const float* __restrict__ scale3,
    const float* __restrict__ shift3,
    const float* __restrict__ wsc, const float* __restrict__ scale_sc,
    const float* __restrict__ shift_sc,
    float* __restrict__ out)
{
    __shared__ __align__(16) float sX[2][16][64];
    __shared__ __align__(16) float sW[2][16][160];  // 80 oc duplicated
    const int tid = threadIdx.x;
    const int tx = tid & 15, ty = tid >> 4;          // tx: 4hw, ty: 8oc (0..9)
    const int n = blockIdx.z;
    const int oc_base = blockIdx.y * 80;             // stays inside a 160-oc group
    const int hw0 = blockIdx.x * 64;
    const int gsel = oc_base / 160;

    const float* y2g = g_y2 + ((size_t)n * MID + gsel * 40) * HW;
    const float* xn  = x + (size_t)n * CIN * HW;

    u64 acc[8][2];
    #pragma unroll
    for (int i = 0; i < 8; i++) { acc[i][0] = 0ull; acc[i][1] = 0ull; }
    float2 yr[8][2];

    float rX[7], rW[8];

    auto ldg_tile = [&](int t) {
        if (t < 3) {                                  // conv3 K: 0..47 (valid < 40)
            const int kk = t * 16;
            #pragma unroll
            for (int i = 0; i < 7; i++) {
                int idx = tid + i * 160;
                if (idx < 1024) {
                    int k = idx >> 6, j = idx & 63, kg = kk + k;
                    rX[i] = (kg < 40) ? y2g[(size_t)kg * HW + hw0 + j] : 0.f;
                }
            }
            #pragma unroll
            for (int i = 0; i < 8; i++) {             // 16*80 = 1280 = 8*160
                int idx = tid + i * 160;
                int oc = idx >> 4, k = idx & 15, kg = kk + k;
                rW[i] = (kg < 40) ? w3[(oc_base + oc) * 40 + kg] : 0.f;
            }
        } else {                                      // shortcut K: 0..239
            const int kk = (t - 3) * 16;
            #pragma unroll
            for (int i = 0; i < 7; i++) {
                int idx = tid + i * 160;
                if (idx < 1024) {
                    int k = idx >> 6, j = idx & 63;
                    rX[i] = xn[(size_t)(kk + k) * HW + hw0 + j];
                }
            }
            #pragma unroll
            for (int i = 0; i < 8; i++) {
                int idx = tid + i * 160;
                int oc = idx >> 4, k = idx & 15;
                rW[i] = wsc[(oc_base + oc) * 240 + kk + k];
            }
        }
    };
    auto sts_tile = [&](int b) {
        #pragma unroll
        for (int i = 0; i < 7; i++) {
            int idx = tid + i * 160;
            if (idx < 1024) { int k = idx >> 6, j = idx & 63; sX[b][k][j] = rX[i]; }
        }
        #pragma unroll
        for (int i = 0; i < 8; i++) {
            int idx = tid + i * 160;
            int oc = idx >> 4, k = idx & 15;
            sW[b][k][2 * oc] = rW[i];
            sW[b][k][2 * oc + 1] = rW[i];
        }
    };
    auto compute = [&](int b) {
        #pragma unroll
        for (int k = 0; k < 16; k++) {
            const ulonglong2 w01 = *(const ulonglong2*)&sW[b][k][ty * 16];
            const ulonglong2 w23 = *(const ulonglong2*)&sW[b][k][ty * 16 + 4];
            const ulonglong2 w45 = *(const ulonglong2*)&sW[b][k][ty * 16 + 8];
            const ulonglong2 w67 = *(const ulonglong2*)&sW[b][k][ty * 16 + 12];
            const ulonglong2 xp  = *(const ulonglong2*)&sX[b][k][tx * 4];
            acc[0][0] = fma2(w01.x, xp.x, acc[0][0]); acc[0][1] = fma2(w01.x, xp.y, acc[0][1]);
            acc[1][0] = fma2(w01.y, xp.x, acc[1][0]); acc[1][1] = fma2(w01.y, xp.y, acc[1][1]);
            acc[2][0] = fma2(w23.x, xp.x, acc[2][0]); acc[2][1] = fma2(w23.x, xp.y, acc[2][1]);
            acc[3][0] = fma2(w23.y, xp.x, acc[3][0]); acc[3][1] = fma2(w23.y, xp.y, acc[3][1]);
            acc[4][0] = fma2(w45.x, xp.x, acc[4][0]); acc[4][1] = fma2(w45.x, xp.y, acc[4][1]);
            acc[5][0] = fma2(w45.y, xp.x, acc[5][0]); acc[5][1] = fma2(w45.y, xp.y, acc[5][1]);
            acc[6][0] = fma2(w67.x, xp.x, acc[6][0]); acc[6][1] = fma2(w67.x, xp.y, acc[6][1]);
            acc[7][0] = fma2(w67.y, xp.x, acc[7][0]); acc[7][1] = fma2(w67.y, xp.y, acc[7][1]);
        }
    };

    ldg_tile(0); sts_tile(0); __syncthreads();
    for (int t = 0; t < 18; t++) {
        int b = t & 1;
        if (t + 1 < 18) ldg_tile(t + 1);
        compute(b);
        if (t == 2) {   // conv3 done: fold BN3 + ReLU into registers, reset acc
            #pragma unroll
            for (int i = 0; i < 8; i++) {
                int oc = oc_base + ty * 8 + i;
                float sc = scale3[oc], sh = shift3[oc];
                #pragma unroll
                for (int p = 0; p < 2; p++) {
                    float2 v = unpack2(acc[i][p]);
                    yr[i][p].x = fmaxf(fmaf(v.x, sc, sh), 0.f);
                    yr[i][p].y = fmaxf(fmaf(v.y, sc, sh), 0.f);
                    acc[i][p] = 0ull;
                }
            }
        }
        if (t + 1 < 18) sts_tile(b ^ 1);
        __syncthreads();
    }

    // final: relu(BN3(conv3)) + BN_sc(shortcut), float4 stores
    float* ob = out + (size_t)n * COUT * HW;
    #pragma unroll
    for (int i = 0; i < 8; i++) {
        int oc = oc_base + ty * 8 + i;
        float ss = scale_sc[oc], sb = shift_sc[oc];
        float2 z0 = unpack2(acc[i][0]), z1 = unpack2(acc[i][1]);
        float4 o;
        o.x = fmaf(z0.x, ss, sb) + yr[i][0].x;
        o.y = fmaf(z0.y, ss, sb) + yr[i][0].y;
        o.z = fmaf(z1.x, ss, sb) + yr[i][1].x;
        o.w = fmaf(z1.y, ss, sb) + yr[i][1].y;
        *(float4*)&ob[(size_t)oc * HW + hw0 + tx * 4] = o;
    }
}

// ---------------------------------------------------------------------------
extern "C" void kernel_launch(void* const* d_in, const int* in_sizes, int n_in,
                              void* d_out, int out_size)
{
    const float* x        = (const float*)d_in[0];
    const float* w1       = (const float*)d_in[1];
    const float* scale1   = (const float*)d_in[2];
    const float* shift1   = (const float*)d_in[3];
    const float* w2       = (const float*)d_in[4];
    const float* scale2   = (const float*)d_in[5];
    const float* shift2   = (const float*)d_in[6];
    const float* w3       = (const float*)d_in[7];
    const float* scale3   = (const float*)d_in[8];
    const float* shift3   = (const float*)d_in[9];
    const float* wsc      = (const float*)d_in[10];
    const float* scale_sc = (const float*)d_in[11];
    const float* shift_sc = (const float*)d_in[12];
    // d_in[13] = groups (always 3), baked in at compile time
    float* out = (float*)d_out;

    conv1_kernel<<<dim3(49, 3, NB), 160>>>(x, w1, scale1, shift1);
    dw_kernel<<<dim3((HW + 255) / 256, MID, NB), 256>>>(w2, scale2, shift2);
    conv3_kernel<<<dim3(49, 6, NB), 160>>>(x, w3, scale3, shift3,
                                           wsc, scale_sc, shift_sc, out);
}

// round 14
// speedup vs baseline: 2.0979x; 2.0979x over previous
#include <cuda_runtime.h>
#include <stdint.h>

#define HW   3136
#define WD   56
#define NB   32
#define CIN  240
#define MID  120
#define COUT 480

// Scratch (allocation-free rule: __device__ globals)
__device__ float g_y1[(size_t)NB * MID * HW];   // conv1 output (post BN+ReLU)
__device__ float g_y2[(size_t)NB * MID * HW];   // depthwise output, SHUFFLED channel order

// Pre-duplicated weight layouts (filled by prep_kernel each call):
//  g_w1d  [g][k=80][80]   : 40 oc duplicated pairwise
//  g_w3d  [g][k=48][320]  : 160 oc duplicated, k padded 40->48 with zeros
//  g_wscd [k=240][960]    : 480 oc duplicated
__device__ float g_w1d[3 * 80 * 80];
__device__ float g_w3d[3 * 48 * 320];
__device__ float g_wscd[240 * 960];

typedef unsigned long long u64;

__device__ __forceinline__ u64 fma2(u64 a, u64 b, u64 c) {
    u64 d; asm("fma.rn.f32x2 %0, %1, %2, %3;" : "=l"(d) : "l"(a), "l"(b), "l"(c)); return d;
}
__device__ __forceinline__ float2 unpack2(u64 v) {
    float2 r; asm("mov.b64 {%0, %1}, %2;" : "=f"(r.x), "=f"(r.y) : "l"(v)); return r;
}
__device__ __forceinline__ uint32_t saddr(const void* p) {
    return (uint32_t)__cvta_generic_to_shared(p);
}
__device__ __forceinline__ void cp16(uint32_t dst, const void* src, int src_size) {
    asm volatile("cp.async.cg.shared.global [%0], [%1], 16, %2;\n"
                 :: "r"(dst), "l"(src), "r"(src_size));
}
#define CP_COMMIT() asm volatile("cp.async.commit_group;\n" ::: "memory")
#define CP_WAIT1()  asm volatile("cp.async.wait_group 1;\n" ::: "memory")
#define CP_WAIT0()  asm volatile("cp.async.wait_group 0;\n" ::: "memory")

// ---------------------------------------------------------------------------
// prep: duplicate weights pairwise into [k][2*oc] layouts (tiny, ~0.5MB writes)
// ---------------------------------------------------------------------------
__global__ __launch_bounds__(256) void prep_kernel(
    const float* __restrict__ w1, const float* __restrict__ w3,
    const float* __restrict__ wsc)
{
    const int tid = blockIdx.x * 256 + threadIdx.x;
    if (tid < 9600) {                     // w1: 3 groups x 40 oc x 80 k
        int g = tid / 3200, r = tid % 3200;
        int oc = r / 80, k = r % 80;
        float v = w1[(g * 40 + oc) * 80 + k];
        float* d = g_w1d + ((size_t)(g * 80 + k)) * 80 + 2 * oc;
        d[0] = v; d[1] = v;
    }
    if (tid < 23040) {                    // w3: 3 groups x 160 oc x 48 k (pad)
        int g = tid / 7680, r = tid % 7680;
        int oc = r / 48, k = r % 48;
        float v = (k < 40) ? w3[(g * 160 + oc) * 40 + k] : 0.f;
        float* d = g_w3d + ((size_t)(g * 48 + k)) * 320 + 2 * oc;
        d[0] = v; d[1] = v;
    }
    if (tid < 115200) {                   // wsc: 480 oc x 240 k
        int oc = tid / 240, k = tid % 240;
        float v = wsc[oc * 240 + k];
        float* d = g_wscd + (size_t)k * 960 + 2 * oc;
        d[0] = v; d[1] = v;
    }
}

// ---------------------------------------------------------------------------
// K1: grouped 1x1 conv (40oc x 80ic per group) + BN + ReLU -> g_y1
// grid (49, 3, 32), block 160.  3-stage cp.async pipeline, 5 K-tiles of 16.
// Inner loop: 8 FFMA2 + 3 LDS.128, zero MOVs (dup-W smem + float4 hw-pairs).
// ---------------------------------------------------------------------------
__global__ __launch_bounds__(160, 8) void conv1_kernel(
    const float* __restrict__ x,
    const float* __restrict__ scale1, const float* __restrict__ shift1)
{
    __shared__ __align__(16) float sX[3][16][64];
    __shared__ __align__(16) float sW[3][16][80];
    const int tid = threadIdx.x;
    const int tx = tid & 15, ty = tid >> 4;          // tx: 4hw, ty: 4oc (0..9)
    const int n = blockIdx.z, g = blockIdx.y;
    const int hw0 = blockIdx.x * 64;
    const float* xg = x + ((size_t)n * CIN + g * 80) * HW + hw0;
    const float* wg = g_w1d + (size_t)g * 80 * 80;

    // X chunk coords (256 chunks of 16B per tile)
    const int kx0 = tid >> 4, jx0 = (tid & 15) * 4;
    const int cx1 = tid + 160;
    const bool hx1 = cx1 < 256;
    const int kx1 = (cx1 >> 4) & 15, jx1 = (cx1 & 15) * 4;
    // W chunk coords (320 chunks per tile, 2 per thread)
    const int kw0 = tid / 20, ow0 = (tid % 20) * 4;
    const int cw1 = tid + 160;
    const int kw1 = cw1 / 20, ow1 = (cw1 % 20) * 4;

    u64 acc[4][2];
    #pragma unroll
    for (int i = 0; i < 4; i++) { acc[i][0] = 0ull; acc[i][1] = 0ull; }

    auto issue = [&](int t) {
        const int b = t % 3, kk = t * 16;
        cp16(saddr(&sX[b][kx0][jx0]), xg + (size_t)(kk + kx0) * HW + jx0, 16);
        if (hx1)
            cp16(saddr(&sX[b][kx1][jx1]), xg + (size_t)(kk + kx1) * HW + jx1, 16);
        cp16(saddr(&sW[b][kw0][ow0]), wg + (size_t)(kk + kw0) * 80 + ow0, 16);
        cp16(saddr(&sW[b][kw1][ow1]), wg + (size_t)(kk + kw1) * 80 + ow1, 16);
        CP_COMMIT();
    };

    issue(0); issue(1);
    for (int t = 0; t < 5; t++) {
        if (t < 4) CP_WAIT1(); else CP_WAIT0();
        __syncthreads();
        const int b = t % 3;
        #pragma unroll
        for (int k = 0; k < 16; k++) {
            const ulonglong2 w01 = *(const ulonglong2*)&sW[b][k][ty * 8];
            const ulonglong2 w23 = *(const ulonglong2*)&sW[b][k][ty * 8 + 4];
            const ulonglong2 xp  = *(const ulonglong2*)&sX[b][k][tx * 4];
            acc[0][0] = fma2(w01.x, xp.x, acc[0][0]); acc[0][1] = fma2(w01.x, xp.y, acc[0][1]);
            acc[1][0] = fma2(w01.y, xp.x, acc[1][0]); acc[1][1] = fma2(w01.y, xp.y, acc[1][1]);
            acc[2][0] = fma2(w23.x, xp.x, acc[2][0]); acc[2][1] = fma2(w23.x, xp.y, acc[2][1]);
            acc[3][0] = fma2(w23.y, xp.x, acc[3][0]); acc[3][1] = fma2(w23.y, xp.y, acc[3][1]);
        }
        if (t + 2 < 5) issue(t + 2);
    }

    float* yb = g_y1 + (size_t)n * MID * HW;
    #pragma unroll
    for (int i = 0; i < 4; i++) {
        int oc = g * 40 + ty * 4 + i;
        float sc = scale1[oc], sh = shift1[oc];
        float2 v0 = unpack2(acc[i][0]), v1 = unpack2(acc[i][1]);
        float4 o;
        o.x = fmaxf(fmaf(v0.x, sc, sh), 0.f);
        o.y = fmaxf(fmaf(v0.y, sc, sh), 0.f);
        o.z = fmaxf(fmaf(v1.x, sc, sh), 0.f);
        o.w = fmaxf(fmaf(v1.y, sc, sh), 0.f);
        *(float4*)&yb[(size_t)oc * HW + hw0 + tx * 4] = o;
    }
}

// ---------------------------------------------------------------------------
// K2: depthwise 3x3 (pad 1) + BN2, write in SHUFFLED channel order.
// source c writes to dst = (c%40)*3 + c/40
// ---------------------------------------------------------------------------
__global__ __launch_bounds__(256) void dw_kernel(
    const float* __restrict__ w2, const float* __restrict__ scale2,
    const float* __restrict__ shift2)
{
    const int n = blockIdx.z, c = blockIdx.y;
    const int p = blockIdx.x * 256 + threadIdx.x;
    if (p >= HW) return;
    const int h = p / WD, w = p % WD;
    const float* src = g_y1 + ((size_t)n * MID + c) * HW;
    const float* wr = w2 + c * 9;
    float s = 0.f;
    #pragma unroll
    for (int kh = 0; kh < 3; kh++) {
        int hh = h + kh - 1;
        if (hh < 0 || hh >= WD) continue;
        const float* row = src + hh * WD;
        #pragma unroll
        for (int kw = 0; kw < 3; kw++) {
            int ww = w + kw - 1;
            if (ww >= 0 && ww < WD) s = fmaf(row[ww], wr[kh * 3 + kw], s);
        }
    }
    float v = fmaf(s, scale2[c], shift2[c]);
    const int dst = (c % 40) * 3 + c / 40;
    g_y2[((size_t)n * MID + dst) * HW + p] = v;
}

// ---------------------------------------------------------------------------
// K3: grouped 1x1 conv3 (40 shuffled ic) + BN3 + ReLU, plus full 1x1 shortcut
// (240 ic) + BN_sc, fused add -> out.
// grid (49, 6, 32), block 160.  Tile 80oc x 64hw; per-thread 8oc x 4hw.
// 18 K-tiles (3 conv3 + 15 shortcut), 3-stage cp.async pipeline, 1 sync/tile.
// Inner loop: 16 FFMA2 + 5 LDS.128, zero MOVs.
// ---------------------------------------------------------------------------
__global__ __launch_bounds__(160, 5) void conv3_kernel(
    const float* __restrict__ x,
    const float* __restrict__ scale3, const float* __restrict__ shift3,
    const float* __restrict__ scale_sc, const float* __restrict__ shift_sc,
    float* __restrict__ out)
{
    __shared__ __align__(16) float sX[3][16][64];
    __shared__ __align__(16) float sW[3][16][160];
    const int tid = threadIdx.x;
    const int tx = tid & 15, ty = tid >> 4;          // tx: 4hw, ty: 8oc (0..9)
    const int n = blockIdx.z;
    const int yq = blockIdx.y;                        // 0..5 -> 80-oc tile
    const int gsel = yq >> 1, half = yq & 1;
    const int oc_base = yq * 80;
    const int hw0 = blockIdx.x * 64;

    const float* y2g  = g_y2 + ((size_t)n * MID + gsel * 40) * HW + hw0;
    const float* xn   = x + (size_t)n * CIN * HW + hw0;
    const float* w3g  = g_w3d + (size_t)(gsel * 48) * 320 + half * 160;
    const float* wscg = g_wscd + (size_t)yq * 160;

    // X chunk coords (256 chunks of 16B per tile)
    const int kx0 = tid >> 4, jx0 = (tid & 15) * 4;
    const int cx1 = tid + 160;
    const bool hx1 = cx1 < 256;
    const int kx1 = (cx1 >> 4) & 15, jx1 = (cx1 & 15) * 4;

    u64 acc[8][2];
    #pragma unroll
    for (int i = 0; i < 8; i++) { acc[i][0] = 0ull; acc[i][1] = 0ull; }
    float2 yr[8][2];

    auto issue = [&](int t) {
        const int b = t % 3;
        if (t < 3) {                                  // conv3: K 0..47, zero-fill k>=40
            const int kk = t * 16;
            const int kg0 = kk + kx0, kg1 = kk + kx1;
            cp16(saddr(&sX[b][kx0][jx0]), y2g + (size_t)kg0 * HW + jx0, kg0 < 40 ? 16 : 0);
            if (hx1)
                cp16(saddr(&sX[b][kx1][jx1]), y2g + (size_t)kg1 * HW + jx1, kg1 < 40 ? 16 : 0);
            #pragma unroll
            for (int i = 0; i < 4; i++) {             // 640 W chunks, 4/thread
                int c = tid + i * 160;
                int k = c / 40, off = (c % 40) * 4;
                cp16(saddr(&sW[b][k][off]), w3g + (size_t)(kk + k) * 320 + off, 16);
            }
        } else {                                      // shortcut: K 0..239
            const int kk = (t - 3) * 16;
            cp16(saddr(&sX[b][kx0][jx0]), xn + (size_t)(kk + kx0) * HW + jx0, 16);
            if (hx1)
                cp16(saddr(&sX[b][kx1][jx1]), xn + (size_t)(kk + kx1) * HW + jx1, 16);
            #pragma unroll
            for (int i = 0; i < 4; i++) {
                int c = tid + i * 160;
                int k = c / 40, off = (c % 40) * 4;
                cp16(saddr(&sW[b][k][off]), wscg + (size_t)(kk + k) * 960 + off, 16);
            }
        }
        CP_COMMIT();
    };

    issue(0); issue(1);
    for (int t = 0; t < 18; t++) {
        if (t < 17) CP_WAIT1(); else CP_WAIT0();
        __syncthreads();
        const int b = t % 3;
        #pragma unroll
        for (int k = 0; k < 16; k++) {
            const ulonglong2 w01 = *(const ulonglong2*)&sW[b][k][ty * 16];
            const ulonglong2 w23 = *(const ulonglong2*)&sW[b][k][ty * 16 + 4];
            const ulonglong2 w45 = *(const ulonglong2*)&sW[b][k][ty * 16 + 8];
            const ulonglong2 w67 = *(const ulonglong2*)&sW[b][k][ty * 16 + 12];
            const ulonglong2 xp  = *(const ulonglong2*)&sX[b][k][tx * 4];
            acc[0][0] = fma2(w01.x, xp.x, acc[0][0]); acc[0][1] = fma2(w01.x, xp.y, acc[0][1]);
            acc[1][0] = fma2(w01.y, xp.x, acc[1][0]); acc[1][1] = fma2(w01.y, xp.y, acc[1][1]);
            acc[2][0] = fma2(w23.x, xp.x, acc[2][0]); acc[2][1] = fma2(w23.x, xp.y, acc[2][1]);
            acc[3][0] = fma2(w23.y, xp.x, acc[3][0]); acc[3][1] = fma2(w23.y, xp.y, acc[3][1]);
            acc[4][0] = fma2(w45.x, xp.x, acc[4][0]); acc[4][1] = fma2(w45.x, xp.y, acc[4][1]);
            acc[5][0] = fma2(w45.y, xp.x, acc[5][0]); acc[5][1] = fma2(w45.y, xp.y, acc[5][1]);
            acc[6][0] = fma2(w67.x, xp.x, acc[6][0]); acc[6][1] = fma2(w67.x, xp.y, acc[6][1]);
            acc[7][0] = fma2(w67.y, xp.x, acc[7][0]); acc[7][1] = fma2(w67.y, xp.y, acc[7][1]);
        }
        if (t == 2) {   // conv3 done: fold BN3 + ReLU into registers, reset acc
            #pragma unroll
            for (int i = 0; i < 8; i++) {
                int oc = oc_base + ty * 8 + i;
                float sc = scale3[oc], sh = shift3[oc];
                #pragma unroll
                for (int p = 0; p < 2; p++) {
                    float2 v = unpack2(acc[i][p]);
                    yr[i][p].x = fmaxf(fmaf(v.x, sc, sh), 0.f);
                    yr[i][p].y = fmaxf(fmaf(v.y, sc, sh), 0.f);
                    acc[i][p] = 0ull;
                }
            }
        }
        if (t + 2 < 18) issue(t + 2);
    }

    // final: relu(BN3(conv3)) + BN_sc(shortcut), float4 stores
    float* ob = out + (size_t)n * COUT * HW;
    #pragma unroll
    for (int i = 0; i < 8; i++) {
        int oc = oc_base + ty * 8 + i;
        float ss = scale_sc[oc], sb = shift_sc[oc];
        float2 z0 = unpack2(acc[i][0]), z1 = unpack2(acc[i][1]);
        float4 o;
        o.x = fmaf(z0.x, ss, sb) + yr[i][0].x;
        o.y = fmaf(z0.y, ss, sb) + yr[i][0].y;
        o.z = fmaf(z1.x, ss, sb) + yr[i][1].x;
        o.w = fmaf(z1.y, ss, sb) + yr[i][1].y;
        *(float4*)&ob[(size_t)oc * HW + hw0 + tx * 4] = o;
    }
}

// ---------------------------------------------------------------------------
extern "C" void kernel_launch(void* const* d_in, const int* in_sizes, int n_in,
                              void* d_out, int out_size)
{
    const float* x        = (const float*)d_in[0];
    const float* w1       = (const float*)d_in[1];
    const float* scale1   = (const float*)d_in[2];
    const float* shift1   = (const float*)d_in[3];
    const float* w2       = (const float*)d_in[4];
    const float* scale2   = (const float*)d_in[5];
    const float* shift2   = (const float*)d_in[6];
    const float* w3       = (const float*)d_in[7];
    const float* scale3   = (const float*)d_in[8];
    const float* shift3   = (const float*)d_in[9];
    const float* wsc      = (const float*)d_in[10];
    const float* scale_sc = (const float*)d_in[11];
    const float* shift_sc = (const float*)d_in[12];
    // d_in[13] = groups (always 3), baked in at compile time
    float* out = (float*)d_out;

    prep_kernel<<<450, 256>>>(w1, w3, wsc);
    conv1_kernel<<<dim3(49, 3, NB), 160>>>(x, scale1, shift1);
    dw_kernel<<<dim3((HW + 255) / 256, MID, NB), 256>>>(w2, scale2, shift2);
    conv3_kernel<<<dim3(49, 6, NB), 160>>>(x, scale3, shift3,
                                           scale_sc, shift_sc, out);
}